// round 17
// baseline (speedup 1.0000x reference)
#include <cuda_runtime.h>
#include <cuda_fp16.h>

#define M_DIM 2048
#define N_DIM 8192
#define N_ITERS 1000
#define TAU 1e-4f
#define SIGMA 1e-4f
#define NBLK 296
#define NTHR 512

#define PROWS 6             // panel rows resident in SMEM (+1 register row)
#define PPAD 304            // padded partial rows: 296 real + 8 static-zero

// ---------------- device globals (allocation-free scratch) ----------------
__device__ float g_xbar[N_DIM];
__device__ float g_lam[M_DIM];
__device__ float g_part[(size_t)PPAD * N_DIM];  // rows 296+ never written
__device__ unsigned g_flags[NBLK * 32];         // 1 flag / 128B line

// ---------------- smem layout (bytes) ----------------
#define OFF_PANEL 0                        // 6 rows x 8192 half = 98304
#define OFF_RED   98304                    // 16x32 fp32 = 2048
#define OFF_Y     (OFF_RED + 2048)         // 8 fp32
#define OFF_X     (OFF_Y + 32)             // 32 fp32
#define OFF_C     (OFF_X + 128)            // 32 fp32
#define OFF_B     (OFF_C + 128)            // 8 fp32
#define SMEM_BYTES (OFF_B + 32)            // ~100.7 KB -> 2 blocks/SM
#define OFF_LAM   0                        // finale reuse of panel: 2048 fp32

// ---------------------------------------------------------------------------
__global__ void init_kernel() {
    int i = blockIdx.x * blockDim.x + threadIdx.x;
    if (i < N_DIM) g_xbar[i] = 0.f;
    if (i < NBLK * 32) g_flags[i] = 0u;
}

// ---- GPU-scope sync primitives (R13-proven) --------------------------------
__device__ __forceinline__ unsigned ld_relaxed(const unsigned* p) {
    unsigned v;
    asm volatile("ld.relaxed.gpu.global.u32 %0, [%1];" : "=r"(v) : "l"(p) : "memory");
    return v;
}
__device__ __forceinline__ void st_release(unsigned* p, unsigned v) {
    asm volatile("st.release.gpu.global.u32 [%0], %1;" :: "l"(p), "r"(v) : "memory");
}
__device__ __forceinline__ void fence_acq() {
    asm volatile("fence.acq_rel.gpu;" ::: "memory");
}
__device__ __forceinline__ void grid_barrier(unsigned target) {
    __syncthreads();
    if (threadIdx.x == 0)
        st_release(&g_flags[blockIdx.x * 32], target);
    if (threadIdx.x < NBLK) {
        while (ld_relaxed(&g_flags[threadIdx.x * 32]) < target) { }
        fence_acq();
    }
    __syncthreads();
}

// convert 8 fp16 (uint4) -> 8 fp32
__device__ __forceinline__ void cvt8(uint4 a, float* f) {
    float2 t;
    t = __half22float2(*reinterpret_cast<__half2*>(&a.x)); f[0] = t.x; f[1] = t.y;
    t = __half22float2(*reinterpret_cast<__half2*>(&a.y)); f[2] = t.x; f[3] = t.y;
    t = __half22float2(*reinterpret_cast<__half2*>(&a.z)); f[4] = t.x; f[5] = t.y;
    t = __half22float2(*reinterpret_cast<__half2*>(&a.w)); f[6] = t.x; f[7] = t.y;
}

// pack 8 fp32 -> uint4 of fp16
__device__ __forceinline__ uint4 pack8(float4 v0, float4 v1) {
    uint4 h;
    *reinterpret_cast<__half2*>(&h.x) = __floats2half2_rn(v0.x, v0.y);
    *reinterpret_cast<__half2*>(&h.y) = __floats2half2_rn(v0.z, v0.w);
    *reinterpret_cast<__half2*>(&h.z) = __floats2half2_rn(v1.x, v1.y);
    *reinterpret_cast<__half2*>(&h.w) = __floats2half2_rn(v1.z, v1.w);
    return h;
}

// ---------------------------------------------------------------------------
__global__ void __launch_bounds__(NTHR, 2)
pdhg_kernel(const float* __restrict__ A, const float* __restrict__ b,
            const float* __restrict__ c, float* __restrict__ out) {
    extern __shared__ char sm[];
    const int tid  = threadIdx.x;
    const int warp = tid >> 5;
    const int lane = tid & 31;
    const int blk  = blockIdx.x;

    const int r0 = (blk * M_DIM) / NBLK;
    const int nr = ((blk + 1) * M_DIM) / NBLK - r0;   // 6 or 7
    const int c0 = (blk * N_DIM) / NBLK;
    const int nc = ((blk + 1) * N_DIM) / NBLK - c0;   // 27 or 28

    float* s_red = (float*)(sm + OFF_RED);
    float* y_sm  = (float*)(sm + OFF_Y);
    float* x_sm  = (float*)(sm + OFF_X);
    float* c_sm  = (float*)(sm + OFF_C);
    float* b_sm  = (float*)(sm + OFF_B);
    const uint4* P4 = (const uint4*)(sm + OFF_PANEL);

    // ---- prologue: convert 6 fp32 rows -> fp16 SMEM panel; 7th -> regs ----
    {
        const float4* A4 = (const float4*)A;
        uint4* W4 = (uint4*)(sm + OFF_PANEL);
        for (int r = 0; r < PROWS; r++) {
            size_t base = ((size_t)(r0 + r)) * 2048 + 4 * tid;
            float4 v0 = A4[base], v1 = A4[base + 1];
            float4 v2 = A4[base + 2], v3 = A4[base + 3];
            W4[r * 1024 + 2 * tid]     = pack8(v0, v1);
            W4[r * 1024 + 2 * tid + 1] = pack8(v2, v3);
        }
        if (tid < 8)  y_sm[tid] = 0.f;
        if (tid < nr) b_sm[tid] = b[r0 + tid];
        if (tid < nc) { x_sm[tid] = 0.f; c_sm[tid] = c[c0 + tid]; }
    }
    uint4 a_s0, a_s1;                      // register row r0+6 (y=0 if padded)
    {
        const float4* A4 = (const float4*)A;
        size_t base = ((size_t)(r0 + PROWS)) * 2048 + 4 * tid;
        a_s0 = pack8(A4[base], A4[base + 1]);
        a_s1 = pack8(A4[base + 2], A4[base + 3]);
    }
    __syncthreads();

    unsigned epoch = 0;

    for (int it = 0; it < N_ITERS; it++) {
        // ================= Phase Y: y = min(0, y + s*(A@xbar) - s*b) =======
        float v[8];
        {
            const float4* gx4 = (const float4*)g_xbar;
            float4 x0 = __ldcg(gx4 + 4 * tid);
            float4 x1 = __ldcg(gx4 + 4 * tid + 1);
            float4 x2 = __ldcg(gx4 + 4 * tid + 2);
            float4 x3 = __ldcg(gx4 + 4 * tid + 3);

            #pragma unroll
            for (int i = 0; i < 7; i++) {
                uint4 a0 = (i < PROWS) ? P4[i * 1024 + 2 * tid]     : a_s0;
                uint4 a1 = (i < PROWS) ? P4[i * 1024 + 2 * tid + 1] : a_s1;
                float f[8];
                cvt8(a0, f);
                float s = f[0]*x0.x + f[1]*x0.y + f[2]*x0.z + f[3]*x0.w +
                          f[4]*x1.x + f[5]*x1.y + f[6]*x1.z + f[7]*x1.w;
                cvt8(a1, f);
                s += f[0]*x2.x + f[1]*x2.y + f[2]*x2.z + f[3]*x2.w +
                     f[4]*x3.x + f[5]*x3.y + f[6]*x3.z + f[7]*x3.w;
                v[i] = s;
            }
            v[7] = 0.f;
        }
        // butterfly 8-row warp reduction (same recursion as R8's 16-row)
        {
            #pragma unroll
            for (int k = 0; k < 4; k++) {
                float s = (lane & 16) ? v[k] : v[k + 4];
                float r = __shfl_xor_sync(0xffffffffu, s, 16);
                v[k] = ((lane & 16) ? v[k + 4] : v[k]) + r;
            }
            #pragma unroll
            for (int k = 0; k < 2; k++) {
                float s = (lane & 8) ? v[k] : v[k + 2];
                float r = __shfl_xor_sync(0xffffffffu, s, 8);
                v[k] = ((lane & 8) ? v[k + 2] : v[k]) + r;
            }
            {
                float s = (lane & 4) ? v[0] : v[1];
                float r = __shfl_xor_sync(0xffffffffu, s, 4);
                v[0] = ((lane & 4) ? v[1] : v[0]) + r;
            }
            v[0] += __shfl_xor_sync(0xffffffffu, v[0], 2);
            v[0] += __shfl_xor_sync(0xffffffffu, v[0], 1);
            int row = (((lane >> 4) & 1) << 2) | (((lane >> 3) & 1) << 1) |
                      ((lane >> 2) & 1);
            if ((lane & 3) == 0) s_red[row * 16 + warp] = v[0];
        }
        __syncthreads();
        if (warp < 8) {
            float t = (lane < 16) ? s_red[warp * 16 + lane] : 0.f;
            #pragma unroll
            for (int o = 16; o > 0; o >>= 1)
                t += __shfl_down_sync(0xffffffffu, t, o);
            if (lane == 0 && warp < nr)
                y_sm[warp] = fminf(0.f, y_sm[warp] + SIGMA * t - SIGMA * b_sm[warp]);
        }
        __syncthreads();

        // ====== Phase X partials, two register-light half passes ===========
        {
            float o0 = 0.f, o1 = 0.f, o2 = 0.f, o3 = 0.f;
            float o4 = 0.f, o5 = 0.f, o6 = 0.f, o7 = 0.f;
            #pragma unroll
            for (int i = 0; i < 7; i++) {
                float yv = y_sm[i];
                uint4 a = (i < PROWS) ? P4[i * 1024 + 2 * tid] : a_s0;
                float f[8];
                cvt8(a, f);
                o0 += f[0]*yv; o1 += f[1]*yv; o2 += f[2]*yv; o3 += f[3]*yv;
                o4 += f[4]*yv; o5 += f[5]*yv; o6 += f[6]*yv; o7 += f[7]*yv;
            }
            float4* O4 = (float4*)(g_part + (size_t)blk * N_DIM + 16 * tid);
            __stcg(O4,     make_float4(o0, o1, o2, o3));
            __stcg(O4 + 1, make_float4(o4, o5, o6, o7));
        }
        {
            float o0 = 0.f, o1 = 0.f, o2 = 0.f, o3 = 0.f;
            float o4 = 0.f, o5 = 0.f, o6 = 0.f, o7 = 0.f;
            #pragma unroll
            for (int i = 0; i < 7; i++) {
                float yv = y_sm[i];
                uint4 a = (i < PROWS) ? P4[i * 1024 + 2 * tid + 1] : a_s1;
                float f[8];
                cvt8(a, f);
                o0 += f[0]*yv; o1 += f[1]*yv; o2 += f[2]*yv; o3 += f[3]*yv;
                o4 += f[4]*yv; o5 += f[5]*yv; o6 += f[6]*yv; o7 += f[7]*yv;
            }
            float4* O4 = (float4*)(g_part + (size_t)blk * N_DIM + 16 * tid);
            __stcg(O4 + 2, make_float4(o0, o1, o2, o3));
            __stcg(O4 + 3, make_float4(o4, o5, o6, o7));
        }
        grid_barrier(++epoch);

        // ===== Reduce partials: branch-free 19 loads (rows 296+ static 0) ==
        {
            int g  = tid >> 5;            // 0..15
            int jc = tid & 31;
            if (jc < nc) {
                float r = 0.f;
                #pragma unroll
                for (int k = 0; k < 19; k++)
                    r += __ldcg(g_part + (size_t)(g + k * 16) * N_DIM + c0 + jc);
                s_red[g * 32 + jc] = r;
            }
            __syncthreads();
            if (tid < nc) {
                float dot = 0.f;
                #pragma unroll
                for (int gg = 0; gg < 16; gg++) dot += s_red[gg * 32 + tid];
                float xo = x_sm[tid];
                float xn = fmaxf(0.f, xo - TAU * dot - TAU * c_sm[tid]);
                x_sm[tid] = xn;
                __stcg(&g_xbar[c0 + tid], 2.f * xn - xo);
            }
        }
        grid_barrier(++epoch);
    }

    // ---- Finalize: out = [x, lam, nu] ----
    if (tid < nc) out[c0 + tid] = x_sm[tid];
    if (tid < nr) {
        float l = fmaxf(0.f, -y_sm[tid]);
        __stcg(&g_lam[r0 + tid], l);
        out[N_DIM + r0 + tid] = l;
    }
    grid_barrier(++epoch);

    // nu = relu(c - A^T @ lam), against ORIGINAL fp32 A (one pass, accuracy)
    {
        float* s_lam = (float*)(sm + OFF_LAM);
        #pragma unroll
        for (int t = 0; t < 4; t++) {
            int i = t * NTHR + tid;
            if (i < M_DIM) s_lam[i] = __ldcg(&g_lam[i]);
        }
        __syncthreads();

        int g  = tid >> 5;                // 0..15
        int jc = tid & 31;
        if (jc < nc) {
            float acc = 0.f;
            for (int i = g; i < M_DIM; i += 16)
                acc += A[(size_t)i * N_DIM + c0 + jc] * s_lam[i];
            s_red[g * 32 + jc] = acc;
        }
        __syncthreads();
        if (tid < nc) {
            float dot = 0.f;
            #pragma unroll
            for (int gg = 0; gg < 16; gg++) dot += s_red[gg * 32 + tid];
            out[N_DIM + M_DIM + c0 + tid] = fmaxf(0.f, c_sm[tid] - dot);
        }
    }
}

// ---------------------------------------------------------------------------
// kernel_launch: 2 graph nodes (init, pdhg). Inputs (metadata order):
//   d_in[0] = c (8192), d_in[1] = A (2048*8192), d_in[2] = b (2048)
// Output: 18432 floats = concat(x[8192], lam[2048], nu[8192])
// ---------------------------------------------------------------------------
extern "C" void kernel_launch(void* const* d_in, const int* in_sizes, int n_in,
                              void* d_out, int out_size) {
    const float* c = (const float*)d_in[0];
    const float* A = (const float*)d_in[1];
    const float* b = (const float*)d_in[2];
    float* out = (float*)d_out;

    cudaFuncSetAttribute(pdhg_kernel,
                         cudaFuncAttributeMaxDynamicSharedMemorySize, SMEM_BYTES);

    init_kernel<<<37, 256>>>();
    pdhg_kernel<<<NBLK, NTHR, SMEM_BYTES>>>(A, b, c, out);
}